// round 12
// baseline (speedup 1.0000x reference)
#include <cuda_runtime.h>

// Pfaffian of 128x128 skew-symmetric submatrices gathered from a 256x256
// skew matrix F_full (strict lower tri F: F_full[i][j]=F[i(i-1)/2+j], i>j).
//
// One CTA / batch element. Parlett-Reid LTL^T, 2 steps per block, 32 blocks.
// Warp-specialized pipeline:
//   threads 0-127  : head pass (4 lines the next snapshot needs) + snapshot
//   threads 128-1023: bulk rank-2 pair over remaining live region (concurrent)
// Snapshot needs NO internal barrier: the 4 cross-thread scalars are
// recomputed redundantly from A (bit-identical ops).
// Bit-exact vs XLA codegen (rel_err == 0.0 lineage):
//   tau = masked row_k * (1/pivot)  (one __fdiv_rn then __fmul_rn)
//   A'  = fma(-col_r, tau_c, fma(tau_r, col_c, A))  (contracted, step order)
//   pf  = sequential __fmul_rn of pivots

#define N128 128
#define LDA  132
#define NTHR 1024
#define NBULKQ 7           // chunk-interleave groups in bulk crew (896/128)
#define NC4  (N128 / 4)

extern __shared__ float smem[];

__device__ __forceinline__ float4 apply2_f4(float4 a, float t1r, float c1r,
                                            float t2r, float c2r,
                                            float4 t1v, float4 c1v,
                                            float4 t2v, float4 c2v)
{
    const float vx = __fmaf_rn(-c1r, t1v.x, __fmaf_rn(t1r, c1v.x, a.x));
    const float vy = __fmaf_rn(-c1r, t1v.y, __fmaf_rn(t1r, c1v.y, a.y));
    const float vz = __fmaf_rn(-c1r, t1v.z, __fmaf_rn(t1r, c1v.z, a.z));
    const float vw = __fmaf_rn(-c1r, t1v.w, __fmaf_rn(t1r, c1v.w, a.w));
    a.x = __fmaf_rn(-c2r, t2v.x, __fmaf_rn(t2r, c2v.x, vx));
    a.y = __fmaf_rn(-c2r, t2v.y, __fmaf_rn(t2r, c2v.y, vy));
    a.z = __fmaf_rn(-c2r, t2v.z, __fmaf_rn(t2r, c2v.z, vz));
    a.w = __fmaf_rn(-c2r, t2v.w, __fmaf_rn(t2r, c2v.w, vw));
    return a;
}

// tau/col for block at row k (steps k, k+2), reading A already corrected on
// rows k,k+2 and cols k+1,k+3. NO barrier: cross-thread scalars recomputed
// redundantly (bit-identical). Threads 0-127.
__device__ __forceinline__ void snapshot_block(const float* __restrict__ A,
                                               int k,
                                               float* __restrict__ tau1,
                                               float* __restrict__ col1,
                                               float* __restrict__ tau2,
                                               float* __restrict__ col2,
                                               int t, float& pf)
{
    const float pivot1 = A[k * LDA + (k + 1)];
    const float invp1  = __fdiv_rn(1.0f, pivot1);
    const float akt    = A[k * LDA + t];
    const float atk1   = A[t * LDA + (k + 1)];
    const float ak2t   = A[(k + 2) * LDA + t];
    const float atk3   = A[t * LDA + (k + 3)];
    const float ak2k3  = A[(k + 2) * LDA + (k + 3)];
    // redundant per-thread scalars (== tau1[k+2], tau1[k+3], col1[k+2], col1[k+3])
    const float t1k2 = __fmul_rn(A[k * LDA + (k + 2)], invp1);
    const float t1k3 = __fmul_rn(A[k * LDA + (k + 3)], invp1);
    const float c1k2 = A[(k + 2) * LDA + (k + 1)];
    const float c1k3 = A[(k + 3) * LDA + (k + 1)];

    const float t1 = (t > k + 1) ? __fmul_rn(akt, invp1) : 0.0f;
    const float c1 = (t > k + 1) ? atk1 : 0.0f;
    tau1[t] = t1;
    col1[t] = c1;

    const float pivot2 = __fmaf_rn(-c1k2, t1k3, __fmaf_rn(t1k2, c1k3, ak2k3));
    const float invp2  = __fdiv_rn(1.0f, pivot2);
    const float row2    = __fmaf_rn(-c1k2, t1, __fmaf_rn(t1k2, c1, ak2t));
    const float col2raw = __fmaf_rn(-c1, t1k3, __fmaf_rn(t1, c1k3, atk3));
    tau2[t] = (t > k + 3) ? __fmul_rn(row2, invp2) : 0.0f;
    col2[t] = (t > k + 3) ? col2raw : 0.0f;
    if (t == 0) pf = __fmul_rn(__fmul_rn(pf, pivot1), pivot2);
}

__global__ __launch_bounds__(NTHR, 1)
void pfaffian_kernel(const float* __restrict__ x,
                     const float* __restrict__ F,
                     float* __restrict__ out)
{
    float* A    = smem;                          // 128*132
    float* bufs = A + N128 * LDA;                // 2 parities * 4 arrays * 128
    float* sx   = bufs + 2 * 4 * N128;           // 128
    int*   idx  = (int*)(sx + N128);             // 128

    const int b = blockIdx.x;
    const int t = threadIdx.x;

    // ---- load x row + occupancy ranks (threads 0-127) ----
    if (t < N128) sx[t] = x[b * N128 + t];
    __syncthreads();
    if (t < N128) {
        const bool mine = sx[t] > 0.0f;
        int cntBefore = 0, totPos = 0;
        #pragma unroll 8
        for (int l = 0; l < N128; ++l) {
            const bool p = sx[l] > 0.0f;
            totPos += p ? 1 : 0;
            if (l < t) cntBefore += p ? 1 : 0;
        }
        const int pos = mine ? cntBefore : (totPos + (t - cntBefore));
        idx[pos] = mine ? t : (N128 + t);
    }
    __syncthreads();

    // ---- gather A[rr][c] = F_full[idx[rr], idx[c]] (1024 threads) ----
    {
        const int c    = t % N128;
        const int jj   = idx[c];
        const int jtri = jj * (jj - 1) / 2;
        #pragma unroll 4
        for (int rr = t / N128; rr < N128; rr += NTHR / N128) {
            const int i = idx[rr];
            float v;
            if (i > jj)      v =  __ldg(&F[i * (i - 1) / 2 + jj]);
            else if (i < jj) v = -__ldg(&F[jtri + i]);
            else             v = 0.0f;
            A[rr * LDA + c] = v;
        }
    }
    __syncthreads();

    // ---- prologue: snapshot block 0 into parity 0 ----
    float pf = 1.0f;
    if (t < N128)
        snapshot_block(A, 0, bufs, bufs + 128, bufs + 256, bufs + 384, t, pf);

    // ---- 31 pipelined iterations: apply block s, snapshot block s+1 ----
    for (int s = 0; s < 31; ++s) {
        __syncthreads();   // orders prev bulk writes + snapshot buffer writes
        const int k = 4 * s;
        float* cur = bufs + (s & 1) * 512;
        float* nxt = bufs + ((s + 1) & 1) * 512;
        float* tau1p = cur;       float* col1p = cur + 128;
        float* tau2p = cur + 256; float* col2p = cur + 384;
        const float4* T1 = (const float4*)tau1p;
        const float4* C1 = (const float4*)col1p;
        const float4* T2 = (const float4*)tau2p;
        const float4* C2 = (const float4*)col2p;

        if (t < N128) {
            // ---- head: update the lines snapshot s+1 reads ----
            // H1: chunk s+1, rows k+4 .. 127
            {
                const int r = k + 4 + t;
                if (r < N128) {
                    const float t1r = tau1p[r], c1r = col1p[r];
                    const float t2r = tau2p[r], c2r = col2p[r];
                    float4* Ar = (float4*)(A + r * LDA);
                    const int c4 = s + 1;
                    Ar[c4] = apply2_f4(Ar[c4], t1r, c1r, t2r, c2r,
                                       T1[c4], C1[c4], T2[c4], C2[c4]);
                }
            }
            // H2: rows k+4, k+6 for chunks >= s+2
            {
                const int r  = k + 4 + 2 * (t & 1);
                const int c4 = s + 2 + (t >> 1);
                if (c4 < NC4) {
                    const float t1r = tau1p[r], c1r = col1p[r];
                    const float t2r = tau2p[r], c2r = col2p[r];
                    float4* Ar = (float4*)(A + r * LDA);
                    Ar[c4] = apply2_f4(Ar[c4], t1r, c1r, t2r, c2r,
                                       T1[c4], C1[c4], T2[c4], C2[c4]);
                }
            }
            asm volatile("bar.sync 1, 128;" ::: "memory");  // head visible

            // ---- snapshot block s+1 (no internal barrier) ----
            snapshot_block(A, k + 4, nxt, nxt + 128, nxt + 256, nxt + 384,
                           t, pf);
        } else {
            // ---- bulk: remaining live region (disjoint from head lines) ----
            const int u = t - N128;
            const int r = u & 127;          // row
            const int q = u >> 7;           // 0..6
            if (r > k + 3 && r != k + 4 && r != k + 6) {
                const float t1r = tau1p[r], c1r = col1p[r];
                const float t2r = tau2p[r], c2r = col2p[r];
                float4* __restrict__ Ar = (float4*)(A + r * LDA);
                #pragma unroll 3
                for (int c4 = s + 2 + q; c4 < NC4; c4 += NBULKQ)
                    Ar[c4] = apply2_f4(Ar[c4], t1r, c1r, t2r, c2r,
                                       T1[c4], C1[c4], T2[c4], C2[c4]);
            }
        }
    }

    if (t == 0) out[b] = pf;
}

extern "C" void kernel_launch(void* const* d_in, const int* in_sizes, int n_in,
                              void* d_out, int out_size)
{
    const float* x = (const float*)d_in[0];   // (B, 128) fp32
    const float* F = (const float*)d_in[1];   // 256*255/2 fp32
    float* out = (float*)d_out;               // (B,) fp32

    const int B = in_sizes[0] / N128;

    // A (128*132) + double-buffered tau/col (1024) + sx (128) + idx (128)
    const size_t shmem = (size_t)(N128 * LDA + 2 * 4 * N128 + 2 * N128)
                         * sizeof(float);

    cudaFuncSetAttribute(pfaffian_kernel,
                         cudaFuncAttributeMaxDynamicSharedMemorySize,
                         (int)shmem);

    pfaffian_kernel<<<B, NTHR, shmem>>>(x, F, out);
}